// round 17
// baseline (speedup 1.0000x reference)
#include <cuda_runtime.h>
#include <cstdint>

// HierarchicalLoss on GB300 sm_103a — R17: single 8-row buffer + LDS.64 edges.
//
// loss = mean(level_w[n] * (softplus(x) - x*t))
//      + 0.5/(B*N) * sum_{b,e} relu(sigmoid(x[b,dst_e]) - sigmoid(x[b,src_e]))
//
// R16 calibration: kernel is near its schedule capability; the cuttable work
// is the DOUBLED edge pass (once per 4-row block). This version packs all
// 8 rows of a column into one uint2 (word.x = rows0-3, word.y = rows4-7,
// 32KB smem) so one LDS.64 fetches a node's 8 rows and the edge pass runs
// ONCE: LDS instructions and edge-index loads halve.
//
// 512 CTAs x 512 thr (16 warps), 4 CTAs/SM. Quantized-u8 edge math
// (__vsubus4 + __dp4a, exact int sum, /255 at end) — validated 5.5e-7.

#define B_DIM 4096
#define N_DIM 4096
#define E_DIM 16384
#define ROWS_PER_CTA 8
#define NUM_CTAS (B_DIM / ROWS_PER_CTA)      // 512
#define THREADS 512
#define NWARPS (THREADS / 32)                 // 16
#define NF4 (N_DIM / 4)                       // 1024 float4 columns per row
#define NITERS_E (E_DIM / 32)                 // 512 warp-iters over all edges

__device__ double             g_part_bce[NUM_CTAS];
__device__ unsigned long long g_part_cons[NUM_CTAS];
__device__ unsigned int       g_done;   // monotonic; 2^32 is a multiple of 512

// One element: weighted BCE accumulate + u8-quantized sigmoid byte.
#define HL_ELEM(xv, tv, wv, pkr, rsh)                                          \
    {   float e = __expf(-(xv)); float u = 1.f + e; float lp = __logf(u);      \
        acc = fmaf((wv), fmaf((xv), 1.f - (tv), lp), acc);                     \
        (pkr) |= __float2uint_rn(__fdividef(255.f, u)) << (8 * (rsh)); }

// Process 4 rows (rowbase..rowbase+3) of float4-column f into 4 packed words,
// stored immediately to probs_u32[2*(4f+j) + sel] (sel: 0 = .x, 1 = .y).
// Two 2-row half-batches: 4 independent LDG.128 front-batched each.
__device__ __forceinline__ float hl_rows4(const float4* __restrict__ o4,
                                          const float4* __restrict__ t4,
                                          float4 w4,
                                          unsigned* __restrict__ probs_u32,
                                          int rowbase, int f, int sel) {
    float acc = 0.f;
    const size_t base = (size_t)rowbase * NF4 + f;
    unsigned pk0 = 0, pk1 = 0, pk2 = 0, pk3 = 0;
    {
        const float4 X0 = o4[base];
        const float4 X1 = o4[base + NF4];
        const float4 T0 = t4[base];
        const float4 T1 = t4[base + NF4];
        HL_ELEM(X0.x, T0.x, w4.x, pk0, 0) HL_ELEM(X0.y, T0.y, w4.y, pk1, 0)
        HL_ELEM(X0.z, T0.z, w4.z, pk2, 0) HL_ELEM(X0.w, T0.w, w4.w, pk3, 0)
        HL_ELEM(X1.x, T1.x, w4.x, pk0, 1) HL_ELEM(X1.y, T1.y, w4.y, pk1, 1)
        HL_ELEM(X1.z, T1.z, w4.z, pk2, 1) HL_ELEM(X1.w, T1.w, w4.w, pk3, 1)
    }
    {
        const float4 X2 = o4[base + 2 * NF4];
        const float4 X3 = o4[base + 3 * NF4];
        const float4 T2 = t4[base + 2 * NF4];
        const float4 T3 = t4[base + 3 * NF4];
        HL_ELEM(X2.x, T2.x, w4.x, pk0, 2) HL_ELEM(X2.y, T2.y, w4.y, pk1, 2)
        HL_ELEM(X2.z, T2.z, w4.z, pk2, 2) HL_ELEM(X2.w, T2.w, w4.w, pk3, 2)
        HL_ELEM(X3.x, T3.x, w4.x, pk0, 3) HL_ELEM(X3.y, T3.y, w4.y, pk1, 3)
        HL_ELEM(X3.z, T3.z, w4.z, pk2, 3) HL_ELEM(X3.w, T3.w, w4.w, pk3, 3)
    }
    const int w0 = 2 * (4 * f) + sel;
    probs_u32[w0]     = pk0;
    probs_u32[w0 + 2] = pk1;
    probs_u32[w0 + 4] = pk2;
    probs_u32[w0 + 6] = pk3;
    return acc;
}

__global__ __launch_bounds__(THREADS, 4)
void hl_fused_kernel(const float* __restrict__ outputs,
                     const float* __restrict__ targets,
                     const float* __restrict__ level_w,
                     const int* __restrict__ edge_src,
                     const int* __restrict__ edge_dst,
                     float* __restrict__ out) {
    __shared__ uint2    probs[N_DIM];         // 32 KB: .x rows0-3, .y rows4-7
    __shared__ double   s_red_b[NWARPS];
    __shared__ double   s_red_c[NWARPS];
    __shared__ unsigned s_last;

    unsigned* probs_u32 = reinterpret_cast<unsigned*>(probs);

    const int tid  = threadIdx.x;
    const int warp = tid >> 5;
    const int lane = tid & 31;
    const int rbase = blockIdx.x * ROWS_PER_CTA;

    const float4* __restrict__ o4  = reinterpret_cast<const float4*>(outputs);
    const float4* __restrict__ t4  = reinterpret_cast<const float4*>(targets);
    const float4* __restrict__ w4p = reinterpret_cast<const float4*>(level_w);

    float    bce  = 0.f;
    unsigned cons = 0;

    // ---- Phase 1: stream all 8 rows, pack into uint2 per column ----
#pragma unroll 1
    for (int i = 0; i < 2; ++i) {
        const int f = tid + 512 * i;
        const float4 w4 = w4p[f];
        bce += hl_rows4(o4, t4, w4, probs_u32, rbase,     f, 0);  // rows 0-3
        bce += hl_rows4(o4, t4, w4, probs_u32, rbase + 4, f, 1);  // rows 4-7
    }
    __syncthreads();

    // ---- Phase 2: edges once, 8 rows per LDS.64 ----
    {
        const int it0 = warp * (NITERS_E / NWARPS);   // 32 iters per warp
        unsigned c0 = 0, c1 = 0, c2 = 0, c3 = 0;
#pragma unroll 1
        for (int it = it0; it < it0 + NITERS_E / NWARPS; it += 2) {
            const int i0 = it * 32 + lane;
            const unsigned d0 = (unsigned)__ldg(edge_dst + i0);
            const unsigned s0 = (unsigned)__ldg(edge_src + i0);
            const unsigned d1 = (unsigned)__ldg(edge_dst + i0 + 32);
            const unsigned s1 = (unsigned)__ldg(edge_src + i0 + 32);
            const uint2 a0 = probs[d0];
            const uint2 b0 = probs[s0];
            const uint2 a1 = probs[d1];
            const uint2 b1 = probs[s1];
            c0 = __dp4a(__vsubus4(a0.x, b0.x), 0x01010101u, c0);
            c1 = __dp4a(__vsubus4(a0.y, b0.y), 0x01010101u, c1);
            c2 = __dp4a(__vsubus4(a1.x, b1.x), 0x01010101u, c2);
            c3 = __dp4a(__vsubus4(a1.y, b1.y), 0x01010101u, c3);
        }
        cons = (c0 + c1) + (c2 + c3);
    }

    // ---- CTA reduction ----
#pragma unroll
    for (int o = 16; o; o >>= 1) {
        bce  += __shfl_xor_sync(0xffffffffu, bce, o);
        cons += __shfl_xor_sync(0xffffffffu, cons, o);
    }
    if (lane == 0) { s_red_b[warp] = (double)bce; s_red_c[warp] = (double)cons; }
    __syncthreads();

    if (tid == 0) {
        double tb_ = 0.0, tc_ = 0.0;
#pragma unroll
        for (int w = 0; w < NWARPS; ++w) { tb_ += s_red_b[w]; tc_ += s_red_c[w]; }
        g_part_bce[blockIdx.x]  = tb_;
        g_part_cons[blockIdx.x] = (unsigned long long)(long long)tc_;
        __threadfence();
        const unsigned old = atomicAdd(&g_done, 1u);
        s_last = (((old + 1u) & (NUM_CTAS - 1u)) == 0u) ? 1u : 0u;
    }
    __syncthreads();

    // ---- Last CTA finalizes (512 partials, 512 threads -> 1 each) ----
    if (s_last) {
        __threadfence();
        double vb = __ldcg(&g_part_bce[tid]);
        double vc = (double)__ldcg(&g_part_cons[tid]);
#pragma unroll
        for (int o = 16; o; o >>= 1) {
            vb += __shfl_xor_sync(0xffffffffu, vb, o);
            vc += __shfl_xor_sync(0xffffffffu, vc, o);
        }
        if (lane == 0) { s_red_b[warp] = vb; s_red_c[warp] = vc; }
        __syncthreads();
        if (tid == 0) {
            double B_ = 0.0, C_ = 0.0;
#pragma unroll
            for (int w = 0; w < NWARPS; ++w) { B_ += s_red_b[w]; C_ += s_red_c[w]; }
            const double denom = (double)B_DIM * (double)N_DIM;
            out[0] = (float)((B_ + 0.5 * (C_ / 255.0)) / denom);
        }
    }
}

extern "C" void kernel_launch(void* const* d_in, const int* in_sizes, int n_in,
                              void* d_out, int out_size) {
    (void)in_sizes; (void)n_in; (void)out_size;
    hl_fused_kernel<<<NUM_CTAS, THREADS>>>(
        (const float*)d_in[0], (const float*)d_in[1], (const float*)d_in[2],
        (const int*)d_in[3], (const int*)d_in[4], (float*)d_out);
}